// round 11
// baseline (speedup 1.0000x reference)
#include <cuda_runtime.h>
#include <cstdint>
#include <math.h>

// Problem constants (fixed by setup_inputs: B=64, N=1024, DEG=16, D=128)
#define D       128
#define BG      64
#define NPG0    1024
#define NN0     (BG * NPG0)        // 65536 nodes layer 1
#define EDGES   (BG * NPG0 * 16)   // 1048576 edges
#define EPG     16384              // CSR capacity per graph
#define K1      820
#define K2      656
#define K3      525
#define N1      (BG * K1)          // 52480
#define N2      (BG * K2)          // 41984
#define N3      (BG * K3)          // 33600

// ---------------- scratch (device globals; no allocation allowed) -----------
__device__ float          g_agg[NN0 * D];     // holds MEAN after gather
__device__ float          g_h[NN0 * D];
__device__ float          g_xa[N1 * D];
__device__ float          g_xb[N2 * D];
__device__ float          g_score[NN0];
__device__ int            g_newid[NN0];
__device__ int            g_oldof[N1];
__device__ float          g_vals[N1];
__device__ int            g_src[EDGES];
__device__ int            g_dst[EDGES];
__device__ unsigned char  g_mask[EDGES];
__device__ int            g_ecnt[NN0];
__device__ int            g_eoff[NN0];
__device__ int            g_ecur[NN0];
__device__ int            g_csr[EDGES];
__device__ float          g_s[BG * 256];
__device__ float          g_invnorm3[3];
__device__ float          g_Bhi[3 * 256 * 128];   // tf32-hi of [Wl;Wr], per layer
__device__ float          g_Blo[3 * 256 * 128];   // tf32-lo of [Wl;Wr], per layer

__device__ __forceinline__ const float* sel_in(const float* ext, int sel) {
    return (sel == 1) ? g_xa : (sel == 2) ? g_xb : ext;
}
__device__ __forceinline__ float* sel_out(int sel) {
    return (sel == 1) ? g_xa : g_xb;
}

// ===================== tf32 mma helpers (sm_80+, no 'a' features) ===========
__device__ __forceinline__ void mma_tf32(float* d,
    uint32_t a0, uint32_t a1, uint32_t a2, uint32_t a3,
    uint32_t b0, uint32_t b1)
{
    asm volatile(
        "mma.sync.aligned.m16n8k8.row.col.f32.tf32.tf32.f32 "
        "{%0,%1,%2,%3}, {%4,%5,%6,%7}, {%8,%9}, {%0,%1,%2,%3};"
        : "+f"(d[0]), "+f"(d[1]), "+f"(d[2]), "+f"(d[3])
        : "r"(a0), "r"(a1), "r"(a2), "r"(a3), "r"(b0), "r"(b1));
}

__device__ __forceinline__ void f32_to_tf32x2(float v, uint32_t& hi, uint32_t& lo) {
    asm("cvt.rna.tf32.f32 %0, %1;" : "=r"(hi) : "f"(v));
    float r = v - __uint_as_float(hi);
    asm("cvt.rna.tf32.f32 %0, %1;" : "=r"(lo) : "f"(r));
}

// ===================== prolog: weight splits + zeroing + invnorms ===========
// blocks [0,384): split 3x(256x128) weights
// blocks [384,640): zero g_ecnt (65536)
// blocks [640,704): zero g_s (16384)
// blocks [704,707): invnorm for pw1..pw3
__global__ void prolog_kernel(
    const float* __restrict__ Wl1, const float* __restrict__ Wr1,
    const float* __restrict__ Wl2, const float* __restrict__ Wr2,
    const float* __restrict__ Wl3, const float* __restrict__ Wr3,
    const float* __restrict__ pw1, const float* __restrict__ pw2,
    const float* __restrict__ pw3)
{
    int b = blockIdx.x, t = threadIdx.x;
    if (b < 384) {
        int i = b * 256 + t;                    // [0, 98304)
        int layer = i >> 15, j = i & 32767;
        int kg = j >> 7, n = j & 127;
        const float* Wl = (layer == 0) ? Wl1 : (layer == 1) ? Wl2 : Wl3;
        const float* Wr = (layer == 0) ? Wr1 : (layer == 1) ? Wr2 : Wr3;
        float v = (kg < 128) ? Wl[(size_t)kg * 128 + n]
                             : Wr[(size_t)(kg - 128) * 128 + n];
        uint32_t hi, lo; f32_to_tf32x2(v, hi, lo);
        g_Bhi[i] = __uint_as_float(hi);
        g_Blo[i] = __uint_as_float(lo);
    } else if (b < 640) {
        int i = (b - 384) * 256 + t;
        if (i < NN0) g_ecnt[i] = 0;
    } else if (b < 704) {
        int i = (b - 640) * 256 + t;
        g_s[i] = 0.0f;
    } else {
        int layer = b - 704;
        const float* pw = (layer == 0) ? pw1 : (layer == 1) ? pw2 : pw3;
        __shared__ float red[256];
        float v = (t < 128) ? pw[t] : 0.0f;
        red[t] = v * v;
        __syncthreads();
        for (int s = 128; s > 0; s >>= 1) {
            if (t < s) red[t] += red[t + s];
            __syncthreads();
        }
        if (t == 0) g_invnorm3[layer] = rsqrtf(red[0]);
    }
}

// ===================== init + layer-1 degree count ==========================
__global__ void init_count_kernel(const int* __restrict__ ei) {
    int i = blockIdx.x * blockDim.x + threadIdx.x;
    if (i < EDGES) {
        int s = ei[i], d = ei[EDGES + i];
        g_src[i] = s;
        g_dst[i] = d;
        g_mask[i] = 1;
        atomicAdd(&g_ecnt[d], 1);
    }
}

// ===================== CSR scan + fill ======================================
__global__ __launch_bounds__(1024) void escan_kernel(int Npg) {
    __shared__ int sc[1024];
    int g = blockIdx.x, t = threadIdx.x;
    int node = g * Npg + t;
    int v = (t < Npg) ? g_ecnt[node] : 0;
    sc[t] = v;
    __syncthreads();
    for (int o = 1; o < 1024; o <<= 1) {
        int a = (t >= o) ? sc[t - o] : 0;
        __syncthreads();
        sc[t] += a;
        __syncthreads();
    }
    if (t < Npg) {
        int off = g * EPG + sc[t] - v;   // exclusive
        g_eoff[node] = off;
        g_ecur[node] = off;
    }
}

__global__ void efill_kernel() {
    int e = blockIdx.x * blockDim.x + threadIdx.x;
    if (e >= EDGES) return;
    if (!g_mask[e]) return;
    int pos = atomicAdd(&g_ecur[g_dst[e]], 1);
    g_csr[pos] = g_src[e];
}

// ===================== gather-mean: g_agg[node] = mean_j x[src_j] ===========
__global__ void gather_mean_kernel(const float* __restrict__ x_ext, int xsel, int n) {
    int gid  = blockIdx.x * blockDim.x + threadIdx.x;
    int node = gid >> 5;
    if (node >= n) return;
    int lane = gid & 31;
    const float* x = sel_in(x_ext, xsel);
    int off = g_eoff[node], cnt = g_ecnt[node];

    float4 acc = make_float4(0.f, 0.f, 0.f, 0.f);
    int i = 0;
    for (; i + 4 <= cnt; i += 4) {
        int s0 = g_csr[off + i], s1 = g_csr[off + i + 1];
        int s2 = g_csr[off + i + 2], s3 = g_csr[off + i + 3];
        float4 v0 = ((const float4*)(x + (size_t)s0 * D))[lane];
        float4 v1 = ((const float4*)(x + (size_t)s1 * D))[lane];
        float4 v2 = ((const float4*)(x + (size_t)s2 * D))[lane];
        float4 v3 = ((const float4*)(x + (size_t)s3 * D))[lane];
        acc.x += v0.x + v1.x + v2.x + v3.x;
        acc.y += v0.y + v1.y + v2.y + v3.y;
        acc.z += v0.z + v1.z + v2.z + v3.z;
        acc.w += v0.w + v1.w + v2.w + v3.w;
    }
    for (; i < cnt; i++) {
        int s = g_csr[off + i];
        float4 v = ((const float4*)(x + (size_t)s * D))[lane];
        acc.x += v.x; acc.y += v.y; acc.z += v.z; acc.w += v.w;
    }
    float inv = 1.0f / (float)max(cnt, 1);
    acc.x *= inv; acc.y *= inv; acc.z *= inv; acc.w *= inv;
    ((float4*)(g_agg + (size_t)node * D))[lane] = acc;
}

// ===================== fused SAGE GEMM (mma.sync tf32x3) + score ============
#define AS_STRIDE 20
#define BS_STRIDE 136
#define AS_WORDS  (128 * AS_STRIDE)
#define BS_WORDS  (16 * BS_STRIDE)
// Ah(2 buf) + Al(2 buf) + Bh(2 buf) + Bl(2 buf)
#define DYN_BYTES ((4 * AS_WORDS + 4 * BS_WORDS) * 4)

__device__ __forceinline__ void sage_gload(float4* ra, float4* rbh, float4* rbl,
    int s, int row0, int n, const float* __restrict__ x,
    const float* __restrict__ BhG, const float* __restrict__ BlG, int tid)
{
    int k0 = s * 16;
#pragma unroll
    for (int p = 0; p < 2; p++) {
        int idx = tid + p * 256;
        int r = idx >> 2, c4 = (idx & 3) << 2;
        int node = row0 + r; if (node >= n) node = n - 1;
        float4 v;
        if (k0 < 128) {
            v = *(const float4*)(g_agg + (size_t)node * D + k0 + c4);
        } else {
            v = *(const float4*)(x + (size_t)node * D + (k0 - 128) + c4);
        }
        ra[p] = v;
        int k = idx >> 5, n4 = (idx & 31) << 2;
        size_t woff = (size_t)(k0 + k) * 128 + n4;
        rbh[p] = *(const float4*)(BhG + woff);
        rbl[p] = *(const float4*)(BlG + woff);
    }
}

__device__ __forceinline__ void sage_sstore(const float4* ra, const float4* rbh,
    const float4* rbl, float* Ah, float* Al, float* Bh, float* Bl, int tid)
{
#pragma unroll
    for (int p = 0; p < 2; p++) {
        int idx = tid + p * 256;
        int r = idx >> 2, c4 = (idx & 3) << 2;
        float4 h4, l4;
        uint32_t uh, ul;
        f32_to_tf32x2(ra[p].x, uh, ul); h4.x = __uint_as_float(uh); l4.x = __uint_as_float(ul);
        f32_to_tf32x2(ra[p].y, uh, ul); h4.y = __uint_as_float(uh); l4.y = __uint_as_float(ul);
        f32_to_tf32x2(ra[p].z, uh, ul); h4.z = __uint_as_float(uh); l4.z = __uint_as_float(ul);
        f32_to_tf32x2(ra[p].w, uh, ul); h4.w = __uint_as_float(uh); l4.w = __uint_as_float(ul);
        *(float4*)(Ah + r * AS_STRIDE + c4) = h4;
        *(float4*)(Al + r * AS_STRIDE + c4) = l4;
        int k = idx >> 5, n4 = (idx & 31) << 2;
        *(float4*)(Bh + k * BS_STRIDE + n4) = rbh[p];
        *(float4*)(Bl + k * BS_STRIDE + n4) = rbl[p];
    }
}

__device__ __forceinline__ void sage_compute(float acc[2][8][4],
    const float* Ah, const float* Al, const float* Bh, const float* Bl,
    int wm, int wn, int l4, int lq)
{
#pragma unroll
    for (int q = 0; q < 2; q++) {
        int kb = q * 8;
        uint32_t ah[2][4], al[2][4];
#pragma unroll
        for (int i = 0; i < 2; i++) {
            int rbase = wm * 32 + i * 16 + l4;
#pragma unroll
            for (int e = 0; e < 4; e++) {
                int rr = rbase + (e & 1) * 8;
                int kk = kb + lq + (e >> 1) * 4;
                ah[i][e] = __float_as_uint(Ah[rr * AS_STRIDE + kk]);
                al[i][e] = __float_as_uint(Al[rr * AS_STRIDE + kk]);
            }
        }
#pragma unroll
        for (int j = 0; j < 8; j++) {
            int nb = wn * 64 + j * 8 + l4;
            uint32_t bh0 = __float_as_uint(Bh[(kb + lq) * BS_STRIDE + nb]);
            uint32_t bh1 = __float_as_uint(Bh[(kb + lq + 4) * BS_STRIDE + nb]);
            uint32_t bl0 = __float_as_uint(Bl[(kb + lq) * BS_STRIDE + nb]);
            uint32_t bl1 = __float_as_uint(Bl[(kb + lq + 4) * BS_STRIDE + nb]);
#pragma unroll
            for (int i = 0; i < 2; i++) {
                mma_tf32(acc[i][j], ah[i][0], ah[i][1], ah[i][2], ah[i][3], bh0, bh1);
                mma_tf32(acc[i][j], ah[i][0], ah[i][1], ah[i][2], ah[i][3], bl0, bl1);
                mma_tf32(acc[i][j], al[i][0], al[i][1], al[i][2], al[i][3], bh0, bh1);
            }
        }
    }
}

__global__ __launch_bounds__(256) void sage_mma_kernel(
    const float* __restrict__ x_ext, int xsel,
    const float* __restrict__ bl, const float* __restrict__ pw,
    int layer, int n)
{
    extern __shared__ float dyn[];
    float* Ah = dyn;                       // 2 x AS_WORDS
    float* Al = dyn + 2 * AS_WORDS;        // 2 x AS_WORDS
    float* Bh = dyn + 4 * AS_WORDS;        // 2 x BS_WORDS
    float* Bl = Bh + 2 * BS_WORDS;         // 2 x BS_WORDS
    __shared__ float sBias[128], sPw[128];
    __shared__ float sDot[128][2];

    const float* x = sel_in(x_ext, xsel);
    const float* BhG = g_Bhi + (size_t)layer * 32768;
    const float* BlG = g_Blo + (size_t)layer * 32768;
    int tid = threadIdx.x;
    int wid = tid >> 5, lane = tid & 31;
    int wm = wid & 3, wn = wid >> 2;
    int l4 = lane >> 2, lq = lane & 3;
    int row0 = blockIdx.x * 128;

    if (tid < 128) {
        sBias[tid] = bl[tid];
        sPw[tid]   = pw[tid];
    }
    __syncthreads();

    float acc[2][8][4];
#pragma unroll
    for (int i = 0; i < 2; i++)
#pragma unroll
        for (int j = 0; j < 8; j++)
#pragma unroll
            for (int e = 0; e < 4; e++) acc[i][j][e] = 0.0f;

    float4 ra[2], rbh[2], rbl[2];
    sage_gload(ra, rbh, rbl, 0, row0, n, x, BhG, BlG, tid);
    sage_sstore(ra, rbh, rbl, Ah, Al, Bh, Bl, tid);
    __syncthreads();

#pragma unroll 1
    for (int s = 0; s < 16; s++) {
        int cur = s & 1, nxt = cur ^ 1;
        if (s < 15) sage_gload(ra, rbh, rbl, s + 1, row0, n, x, BhG, BlG, tid);
        sage_compute(acc, Ah + cur * AS_WORDS, Al + cur * AS_WORDS,
                     Bh + cur * BS_WORDS, Bl + cur * BS_WORDS, wm, wn, l4, lq);
        if (s < 15) {
            sage_sstore(ra, rbh, rbl, Ah + nxt * AS_WORDS, Al + nxt * AS_WORDS,
                        Bh + nxt * BS_WORDS, Bl + nxt * BS_WORDS, tid);
            __syncthreads();
        }
    }

    // ---- epilogue: bias + relu + store h + fused pool-score dot ----
    float dA[2] = {0.0f, 0.0f}, dB[2] = {0.0f, 0.0f};
#pragma unroll
    for (int i = 0; i < 2; i++) {
        int rA = wm * 32 + i * 16 + l4;
        int nodeA = row0 + rA, nodeB = nodeA + 8;
#pragma unroll
        for (int j = 0; j < 8; j++) {
            int c0 = wn * 64 + j * 8 + 2 * lq;
            float o0 = fmaxf(acc[i][j][0] + sBias[c0],     0.0f);
            float o1 = fmaxf(acc[i][j][1] + sBias[c0 + 1], 0.0f);
            float o2 = fmaxf(acc[i][j][2] + sBias[c0],     0.0f);
            float o3 = fmaxf(acc[i][j][3] + sBias[c0 + 1], 0.0f);
            if (nodeA < n) *(float2*)(g_h + (size_t)nodeA * D + c0) = make_float2(o0, o1);
            if (nodeB < n) *(float2*)(g_h + (size_t)nodeB * D + c0) = make_float2(o2, o3);
            dA[i] += o0 * sPw[c0] + o1 * sPw[c0 + 1];
            dB[i] += o2 * sPw[c0] + o3 * sPw[c0 + 1];
        }
    }
#pragma unroll
    for (int o = 1; o <= 2; o <<= 1) {
        dA[0] += __shfl_xor_sync(0xffffffffu, dA[0], o);
        dA[1] += __shfl_xor_sync(0xffffffffu, dA[1], o);
        dB[0] += __shfl_xor_sync(0xffffffffu, dB[0], o);
        dB[1] += __shfl_xor_sync(0xffffffffu, dB[1], o);
    }
    if (lq == 0) {
        sDot[wm * 32 + l4][wn]      = dA[0];
        sDot[wm * 32 + l4 + 8][wn]  = dB[0];
        sDot[wm * 32 + l4 + 16][wn] = dA[1];
        sDot[wm * 32 + l4 + 24][wn] = dB[1];
    }
    __syncthreads();
    if (tid < 128 && row0 + tid < n) {
        float dsum = sDot[tid][0] + sDot[tid][1];
        g_score[row0 + tid] = tanhf(dsum * g_invnorm3[layer]);
    }
}

// ===================== topk (register bitonic) + zero next counts ===========
__global__ __launch_bounds__(1024) void topk_kernel(int Npg, int K, int n_next) {
    __shared__ float ss[1024];
    __shared__ int   si[1024];
    int g = blockIdx.x, t = threadIdx.x;

    // zero next layer's degree counters (ordering to remap_count via kernel boundary)
    int zi = g * 1024 + t;
    if (zi < n_next) g_ecnt[zi] = 0;

    float v = (t < Npg) ? g_score[g * Npg + t] : -1e30f;
    int  id = (t < Npg) ? t : -1;

#pragma unroll 1
    for (int k = 2; k <= 1024; k <<= 1) {
        bool desc = ((t & k) == 0);
#pragma unroll 1
        for (int j = k >> 1; j >= 32; j >>= 1) {
            ss[t] = v; si[t] = id;
            __syncthreads();
            float ov = ss[t ^ j]; int oid = si[t ^ j];
            bool keep_max = (desc == ((t & j) == 0));
            bool take = keep_max ? (ov > v) : (ov < v);
            if (take) { v = ov; id = oid; }
            __syncthreads();
        }
        int j0 = (k >> 1 < 16) ? (k >> 1) : 16;
#pragma unroll 1
        for (int j = j0; j >= 1; j >>= 1) {
            float ov = __shfl_xor_sync(0xffffffffu, v, j);
            int  oid = __shfl_xor_sync(0xffffffffu, id, j);
            bool keep_max = (desc == ((t & j) == 0));
            bool take = keep_max ? (ov > v) : (ov < v);
            if (take) { v = ov; id = oid; }
        }
    }
    if (t < Npg) {
        int oldg = g * Npg + id;
        if (t < K) {
            int nw = g * K + t;
            g_newid[oldg] = nw;
            g_oldof[nw]   = oldg;
            g_vals[nw]    = v;
        } else {
            g_newid[oldg] = -1;
        }
    }
}

// ===================== remap edges + count next-layer degrees ===============
__global__ void remap_count_kernel() {
    int e = blockIdx.x * blockDim.x + threadIdx.x;
    if (e >= EDGES) return;
    if (!g_mask[e]) return;
    int s = g_newid[g_src[e]];
    int d = g_newid[g_dst[e]];
    if (s < 0 || d < 0) { g_mask[e] = 0; g_src[e] = 0; g_dst[e] = 0; }
    else                { g_src[e] = s; g_dst[e] = d; atomicAdd(&g_ecnt[d], 1); }
}

// ===================== fused pool-gather + readout ==========================
// block = graph; 512 threads = 4 node-lanes x 128 feats.
__global__ __launch_bounds__(512) void poolreadout_kernel(int outsel, int K) {
    __shared__ float smax[4][128];
    __shared__ float ssum[4][128];
    float* xout = sel_out(outsel);
    int g = blockIdx.x, t = threadIdx.x;
    int c = t >> 7, f = t & 127;
    float mx = -1e30f, sm = 0.0f;
    for (int k = c; k < K; k += 4) {
        int nw  = g * K + k;
        int old = g_oldof[nw];
        float v = g_vals[nw];
        float val = g_h[(size_t)old * D + f] * v;
        xout[(size_t)nw * D + f] = val;
        mx = fmaxf(mx, val);
        sm += val;
    }
    smax[c][f] = mx; ssum[c][f] = sm;
    __syncthreads();
    if (c == 0) {
#pragma unroll
        for (int i = 1; i < 4; i++) { mx = fmaxf(mx, smax[i][f]); sm += ssum[i][f]; }
        g_s[g * 256 + f]       += mx;
        g_s[g * 256 + 128 + f] += sm / (float)K;
    }
}

// ===================== final MLP head =======================================
__global__ void mlp_kernel(const float* __restrict__ W1, const float* __restrict__ b1,
                           const float* __restrict__ W2, const float* __restrict__ b2,
                           const float* __restrict__ W3, const float* __restrict__ b3,
                           float* __restrict__ out)
{
    __shared__ float ss[256];
    __shared__ float h1[128];
    __shared__ float h2[64];
    int g = blockIdx.x, t = threadIdx.x;   // 128 threads
    ss[t]       = g_s[g * 256 + t];
    ss[t + 128] = g_s[g * 256 + 128 + t];
    __syncthreads();
    float a = b1[t];
    for (int k = 0; k < 256; k++) a += ss[k] * W1[k * 128 + t];
    h1[t] = fmaxf(a, 0.0f);
    __syncthreads();
    if (t < 64) {
        float a2 = b2[t];
        for (int k = 0; k < 128; k++) a2 += h1[k] * W2[k * 64 + t];
        h2[t] = fmaxf(a2, 0.0f);
    }
    __syncthreads();
    if (t == 0) {
        float s2 = 0.0f;
        for (int i = 0; i < 64; i++) s2 += h2[i] * W3[i];
        out[g] = 1.0f / (1.0f + expf(-(s2 + b3[0])));
    }
}

// ===================== host orchestration ===================================
static void run_layer(const float* x_ext, int xsel, int n, int Npg, int K,
                      const float* bl, const float* pw,
                      int layer, int outsel, int n_next)
{
    escan_kernel<<<BG, 1024>>>(Npg);
    efill_kernel<<<(EDGES + 255) / 256, 256>>>();
    gather_mean_kernel<<<(n * 32 + 255) / 256, 256>>>(x_ext, xsel, n);
    sage_mma_kernel<<<(n + 127) / 128, 256, DYN_BYTES>>>(x_ext, xsel, bl, pw, layer, n);
    topk_kernel<<<BG, 1024>>>(Npg, K, n_next);
    if (n_next > 0) remap_count_kernel<<<(EDGES + 255) / 256, 256>>>();
    poolreadout_kernel<<<BG, 512>>>(outsel, K);
}

extern "C" void kernel_launch(void* const* d_in, const int* in_sizes, int n_in,
                              void* d_out, int out_size)
{
    const float* x   = (const float*)d_in[0];
    const int*   ei  = (const int*)  d_in[1];
    const float* Wl1 = (const float*)d_in[2];
    const float* bl1 = (const float*)d_in[3];
    const float* Wr1 = (const float*)d_in[4];
    const float* pw1 = (const float*)d_in[5];
    const float* Wl2 = (const float*)d_in[6];
    const float* bl2 = (const float*)d_in[7];
    const float* Wr2 = (const float*)d_in[8];
    const float* pw2 = (const float*)d_in[9];
    const float* Wl3 = (const float*)d_in[10];
    const float* bl3 = (const float*)d_in[11];
    const float* Wr3 = (const float*)d_in[12];
    const float* pw3 = (const float*)d_in[13];
    const float* W1  = (const float*)d_in[14];
    const float* b1  = (const float*)d_in[15];
    const float* W2  = (const float*)d_in[16];
    const float* b2  = (const float*)d_in[17];
    const float* W3  = (const float*)d_in[18];
    const float* b3  = (const float*)d_in[19];

    cudaFuncSetAttribute(sage_mma_kernel,
                         cudaFuncAttributeMaxDynamicSharedMemorySize, DYN_BYTES);

    prolog_kernel<<<707, 256>>>(Wl1, Wr1, Wl2, Wr2, Wl3, Wr3, pw1, pw2, pw3);
    init_count_kernel<<<(EDGES + 255) / 256, 256>>>(ei);

    run_layer(x,       0, NN0, NPG0, K1, bl1, pw1, 0, 1, N1);
    run_layer(nullptr, 1, N1,  K1,   K2, bl2, pw2, 1, 2, N2);
    run_layer(nullptr, 2, N2,  K2,   K3, bl3, pw3, 2, 1, 0);

    mlp_kernel<<<BG, 128>>>(W1, b1, W2, b2, W3, b3, (float*)d_out);
}

// round 14
// speedup vs baseline: 1.0173x; 1.0173x over previous
#include <cuda_runtime.h>
#include <cstdint>
#include <math.h>

// Problem constants (fixed by setup_inputs: B=64, N=1024, DEG=16, D=128)
#define D       128
#define BG      64
#define NPG0    1024
#define NN0     (BG * NPG0)        // 65536 nodes layer 1
#define EDGES   (BG * NPG0 * 16)   // 1048576 edges
#define EPG     16384              // CSR capacity per graph
#define K1      820
#define K2      656
#define K3      525
#define N1      (BG * K1)          // 52480
#define N2      (BG * K2)          // 41984
#define N3      (BG * K3)          // 33600

// ---------------- scratch (device globals; no allocation allowed) -----------
__device__ float          g_agg[NN0 * D];     // holds MEAN after gather
__device__ float          g_h[NN0 * D];
__device__ float          g_xa[N1 * D];
__device__ float          g_xb[N2 * D];
__device__ float          g_score[NN0];
__device__ int            g_newid[NN0];
__device__ int            g_oldof[N1];
__device__ float          g_vals[N1];
__device__ int            g_src[EDGES];
__device__ int            g_dst[EDGES];
__device__ unsigned char  g_mask[EDGES];
__device__ int            g_ecnt[NN0];
__device__ int            g_eoff[NN0];
__device__ int            g_ecur[NN0];
__device__ int            g_csr[EDGES];
__device__ float          g_s[BG * 256];
__device__ float          g_invnorm3[3];
__device__ float          g_Bhi[3 * 256 * 128];   // tf32-hi of [Wl;Wr], per layer
__device__ float          g_Blo[3 * 256 * 128];   // tf32-lo of [Wl;Wr], per layer

__device__ __forceinline__ const float* sel_in(const float* ext, int sel) {
    return (sel == 1) ? g_xa : (sel == 2) ? g_xb : ext;
}
__device__ __forceinline__ float* sel_out(int sel) {
    return (sel == 1) ? g_xa : g_xb;
}

// ===================== tf32 mma helpers (sm_80+, no 'a' features) ===========
__device__ __forceinline__ void mma_tf32(float* d,
    uint32_t a0, uint32_t a1, uint32_t a2, uint32_t a3,
    uint32_t b0, uint32_t b1)
{
    asm volatile(
        "mma.sync.aligned.m16n8k8.row.col.f32.tf32.tf32.f32 "
        "{%0,%1,%2,%3}, {%4,%5,%6,%7}, {%8,%9}, {%0,%1,%2,%3};"
        : "+f"(d[0]), "+f"(d[1]), "+f"(d[2]), "+f"(d[3])
        : "r"(a0), "r"(a1), "r"(a2), "r"(a3), "r"(b0), "r"(b1));
}

__device__ __forceinline__ void f32_to_tf32x2(float v, uint32_t& hi, uint32_t& lo) {
    asm("cvt.rna.tf32.f32 %0, %1;" : "=r"(hi) : "f"(v));
    float r = v - __uint_as_float(hi);
    asm("cvt.rna.tf32.f32 %0, %1;" : "=r"(lo) : "f"(r));
}

// ===================== prolog: weight splits + zeroing + invnorms ===========
__global__ void prolog_kernel(
    const float* __restrict__ Wl1, const float* __restrict__ Wr1,
    const float* __restrict__ Wl2, const float* __restrict__ Wr2,
    const float* __restrict__ Wl3, const float* __restrict__ Wr3,
    const float* __restrict__ pw1, const float* __restrict__ pw2,
    const float* __restrict__ pw3)
{
    int b = blockIdx.x, t = threadIdx.x;
    if (b < 384) {
        int i = b * 256 + t;                    // [0, 98304)
        int layer = i >> 15, j = i & 32767;
        int kg = j >> 7, n = j & 127;
        const float* Wl = (layer == 0) ? Wl1 : (layer == 1) ? Wl2 : Wl3;
        const float* Wr = (layer == 0) ? Wr1 : (layer == 1) ? Wr2 : Wr3;
        float v = (kg < 128) ? Wl[(size_t)kg * 128 + n]
                             : Wr[(size_t)(kg - 128) * 128 + n];
        uint32_t hi, lo; f32_to_tf32x2(v, hi, lo);
        g_Bhi[i] = __uint_as_float(hi);
        g_Blo[i] = __uint_as_float(lo);
    } else if (b < 640) {
        int i = (b - 384) * 256 + t;
        if (i < NN0) g_ecnt[i] = 0;
    } else if (b < 704) {
        int i = (b - 640) * 256 + t;
        g_s[i] = 0.0f;
    } else {
        int layer = b - 704;
        const float* pw = (layer == 0) ? pw1 : (layer == 1) ? pw2 : pw3;
        __shared__ float red[256];
        float v = (t < 128) ? pw[t] : 0.0f;
        red[t] = v * v;
        __syncthreads();
        for (int s = 128; s > 0; s >>= 1) {
            if (t < s) red[t] += red[t + s];
            __syncthreads();
        }
        if (t == 0) g_invnorm3[layer] = rsqrtf(red[0]);
    }
}

// ===================== init + layer-1 degree count ==========================
__global__ void init_count_kernel(const int* __restrict__ ei) {
    int i = blockIdx.x * blockDim.x + threadIdx.x;
    if (i < EDGES) {
        int s = ei[i], d = ei[EDGES + i];
        g_src[i] = s;
        g_dst[i] = d;
        g_mask[i] = 1;
        atomicAdd(&g_ecnt[d], 1);
    }
}

// ===================== CSR scan + fill ======================================
__global__ __launch_bounds__(1024) void escan_kernel(int Npg) {
    __shared__ int sc[1024];
    int g = blockIdx.x, t = threadIdx.x;
    int node = g * Npg + t;
    int v = (t < Npg) ? g_ecnt[node] : 0;
    sc[t] = v;
    __syncthreads();
    for (int o = 1; o < 1024; o <<= 1) {
        int a = (t >= o) ? sc[t - o] : 0;
        __syncthreads();
        sc[t] += a;
        __syncthreads();
    }
    if (t < Npg) {
        int off = g * EPG + sc[t] - v;   // exclusive
        g_eoff[node] = off;
        g_ecur[node] = off;
    }
}

__global__ void efill_kernel() {
    int e = blockIdx.x * blockDim.x + threadIdx.x;
    if (e >= EDGES) return;
    if (!g_mask[e]) return;
    int pos = atomicAdd(&g_ecur[g_dst[e]], 1);
    g_csr[pos] = g_src[e];
}

// ===================== gather-mean: g_agg[node] = mean_j x[src_j] ===========
__global__ void gather_mean_kernel(const float* __restrict__ x_ext, int xsel, int n) {
    int gid  = blockIdx.x * blockDim.x + threadIdx.x;
    int node = gid >> 5;
    if (node >= n) return;
    int lane = gid & 31;
    const float* x = sel_in(x_ext, xsel);
    int off = g_eoff[node], cnt = g_ecnt[node];

    float4 acc = make_float4(0.f, 0.f, 0.f, 0.f);
    int i = 0;
    for (; i + 4 <= cnt; i += 4) {
        int s0 = g_csr[off + i], s1 = g_csr[off + i + 1];
        int s2 = g_csr[off + i + 2], s3 = g_csr[off + i + 3];
        float4 v0 = ((const float4*)(x + (size_t)s0 * D))[lane];
        float4 v1 = ((const float4*)(x + (size_t)s1 * D))[lane];
        float4 v2 = ((const float4*)(x + (size_t)s2 * D))[lane];
        float4 v3 = ((const float4*)(x + (size_t)s3 * D))[lane];
        acc.x += v0.x + v1.x + v2.x + v3.x;
        acc.y += v0.y + v1.y + v2.y + v3.y;
        acc.z += v0.z + v1.z + v2.z + v3.z;
        acc.w += v0.w + v1.w + v2.w + v3.w;
    }
    for (; i < cnt; i++) {
        int s = g_csr[off + i];
        float4 v = ((const float4*)(x + (size_t)s * D))[lane];
        acc.x += v.x; acc.y += v.y; acc.z += v.z; acc.w += v.w;
    }
    float inv = 1.0f / (float)max(cnt, 1);
    acc.x *= inv; acc.y *= inv; acc.z *= inv; acc.w *= inv;
    ((float4*)(g_agg + (size_t)node * D))[lane] = acc;
}

// ===================== fused SAGE GEMM (mma.sync tf32x3) + score ============
// R9 memory layout: A in fp32 (single copy), B pre-split hi/lo. 54KB dyn smem.
#define AS_STRIDE 20
#define BS_STRIDE 136
#define AS_WORDS  (128 * AS_STRIDE)
#define BS_WORDS  (16 * BS_STRIDE)
#define DYN_BYTES ((2 * AS_WORDS + 4 * BS_WORDS) * 4)

__device__ __forceinline__ void sage_gload(float4* ra, float4* rbh, float4* rbl,
    int s, int row0, int n, const float* __restrict__ x,
    const float* __restrict__ BhG, const float* __restrict__ BlG, int tid)
{
    int k0 = s * 16;
#pragma unroll
    for (int p = 0; p < 2; p++) {
        int idx = tid + p * 256;
        int r = idx >> 2, c4 = (idx & 3) << 2;
        int node = row0 + r; if (node >= n) node = n - 1;
        float4 v;
        if (k0 < 128) {
            v = *(const float4*)(g_agg + (size_t)node * D + k0 + c4);
        } else {
            v = *(const float4*)(x + (size_t)node * D + (k0 - 128) + c4);
        }
        ra[p] = v;
        int k = idx >> 5, n4 = (idx & 31) << 2;
        size_t woff = (size_t)(k0 + k) * 128 + n4;
        rbh[p] = *(const float4*)(BhG + woff);
        rbl[p] = *(const float4*)(BlG + woff);
    }
}

__device__ __forceinline__ void sage_sstore(const float4* ra, const float4* rbh,
    const float4* rbl, float* Ab, float* Bh, float* Bl, int tid)
{
#pragma unroll
    for (int p = 0; p < 2; p++) {
        int idx = tid + p * 256;
        int r = idx >> 2, c4 = (idx & 3) << 2;
        *(float4*)(Ab + r * AS_STRIDE + c4) = ra[p];
        int k = idx >> 5, n4 = (idx & 31) << 2;
        *(float4*)(Bh + k * BS_STRIDE + n4) = rbh[p];
        *(float4*)(Bl + k * BS_STRIDE + n4) = rbl[p];
    }
}

__device__ __forceinline__ void sage_compute(float acc[2][8][4],
    const float* Ab, const float* Bh, const float* Bl,
    int wm, int wn, int l4, int lq)
{
#pragma unroll
    for (int q = 0; q < 2; q++) {
        int kb = q * 8;
        uint32_t ah[2][4], al[2][4];
#pragma unroll
        for (int i = 0; i < 2; i++) {
            int rbase = wm * 32 + i * 16 + l4;
#pragma unroll
            for (int e = 0; e < 4; e++) {
                int rr = rbase + (e & 1) * 8;
                int kk = kb + lq + (e >> 1) * 4;
                f32_to_tf32x2(Ab[rr * AS_STRIDE + kk], ah[i][e], al[i][e]);
            }
        }
#pragma unroll
        for (int j = 0; j < 8; j++) {
            int nb = wn * 64 + j * 8 + l4;
            uint32_t bh0 = __float_as_uint(Bh[(kb + lq) * BS_STRIDE + nb]);
            uint32_t bh1 = __float_as_uint(Bh[(kb + lq + 4) * BS_STRIDE + nb]);
            uint32_t bl0 = __float_as_uint(Bl[(kb + lq) * BS_STRIDE + nb]);
            uint32_t bl1 = __float_as_uint(Bl[(kb + lq + 4) * BS_STRIDE + nb]);
#pragma unroll
            for (int i = 0; i < 2; i++) {
                mma_tf32(acc[i][j], ah[i][0], ah[i][1], ah[i][2], ah[i][3], bh0, bh1);
                mma_tf32(acc[i][j], ah[i][0], ah[i][1], ah[i][2], ah[i][3], bl0, bl1);
                mma_tf32(acc[i][j], al[i][0], al[i][1], al[i][2], al[i][3], bh0, bh1);
            }
        }
    }
}

__global__ __launch_bounds__(256) void sage_mma_kernel(
    const float* __restrict__ x_ext, int xsel,
    const float* __restrict__ bl, const float* __restrict__ pw,
    int layer, int n)
{
    extern __shared__ float dyn[];
    float* As = dyn;                              // 2 x AS_WORDS (fp32 A)
    float* Bh = dyn + 2 * AS_WORDS;               // 2 x BS_WORDS
    float* Bl = Bh + 2 * BS_WORDS;                // 2 x BS_WORDS
    __shared__ float sBias[128], sPw[128];
    __shared__ float sDot[128][2];

    const float* x = sel_in(x_ext, xsel);
    const float* BhG = g_Bhi + (size_t)layer * 32768;
    const float* BlG = g_Blo + (size_t)layer * 32768;
    int tid = threadIdx.x;
    int wid = tid >> 5, lane = tid & 31;
    int wm = wid & 3, wn = wid >> 2;
    int l4 = lane >> 2, lq = lane & 3;
    int row0 = blockIdx.x * 128;

    if (tid < 128) {
        sBias[tid] = bl[tid];
        sPw[tid]   = pw[tid];
    }
    __syncthreads();

    float acc[2][8][4];
#pragma unroll
    for (int i = 0; i < 2; i++)
#pragma unroll
        for (int j = 0; j < 8; j++)
#pragma unroll
            for (int e = 0; e < 4; e++) acc[i][j][e] = 0.0f;

    float4 ra[2], rbh[2], rbl[2];
    sage_gload(ra, rbh, rbl, 0, row0, n, x, BhG, BlG, tid);
    sage_sstore(ra, rbh, rbl, As, Bh, Bl, tid);
    __syncthreads();

#pragma unroll 1
    for (int s = 0; s < 16; s++) {
        int cur = s & 1, nxt = cur ^ 1;
        if (s < 15) sage_gload(ra, rbh, rbl, s + 1, row0, n, x, BhG, BlG, tid);
        sage_compute(acc, As + cur * AS_WORDS, Bh + cur * BS_WORDS,
                     Bl + cur * BS_WORDS, wm, wn, l4, lq);
        if (s < 15) {
            sage_sstore(ra, rbh, rbl, As + nxt * AS_WORDS,
                        Bh + nxt * BS_WORDS, Bl + nxt * BS_WORDS, tid);
            __syncthreads();
        }
    }

    // ---- epilogue: bias + relu + store h + fused pool-score dot ----
    float dA[2] = {0.0f, 0.0f}, dB[2] = {0.0f, 0.0f};
#pragma unroll
    for (int i = 0; i < 2; i++) {
        int rA = wm * 32 + i * 16 + l4;
        int nodeA = row0 + rA, nodeB = nodeA + 8;
#pragma unroll
        for (int j = 0; j < 8; j++) {
            int c0 = wn * 64 + j * 8 + 2 * lq;
            float o0 = fmaxf(acc[i][j][0] + sBias[c0],     0.0f);
            float o1 = fmaxf(acc[i][j][1] + sBias[c0 + 1], 0.0f);
            float o2 = fmaxf(acc[i][j][2] + sBias[c0],     0.0f);
            float o3 = fmaxf(acc[i][j][3] + sBias[c0 + 1], 0.0f);
            if (nodeA < n) *(float2*)(g_h + (size_t)nodeA * D + c0) = make_float2(o0, o1);
            if (nodeB < n) *(float2*)(g_h + (size_t)nodeB * D + c0) = make_float2(o2, o3);
            dA[i] += o0 * sPw[c0] + o1 * sPw[c0 + 1];
            dB[i] += o2 * sPw[c0] + o3 * sPw[c0 + 1];
        }
    }
#pragma unroll
    for (int o = 1; o <= 2; o <<= 1) {
        dA[0] += __shfl_xor_sync(0xffffffffu, dA[0], o);
        dA[1] += __shfl_xor_sync(0xffffffffu, dA[1], o);
        dB[0] += __shfl_xor_sync(0xffffffffu, dB[0], o);
        dB[1] += __shfl_xor_sync(0xffffffffu, dB[1], o);
    }
    if (lq == 0) {
        sDot[wm * 32 + l4][wn]      = dA[0];
        sDot[wm * 32 + l4 + 8][wn]  = dB[0];
        sDot[wm * 32 + l4 + 16][wn] = dA[1];
        sDot[wm * 32 + l4 + 24][wn] = dB[1];
    }
    __syncthreads();
    if (tid < 128 && row0 + tid < n) {
        float dsum = sDot[tid][0] + sDot[tid][1];
        g_score[row0 + tid] = tanhf(dsum * g_invnorm3[layer]);
    }
}

// ===================== topk (register bitonic) + zero next counts ===========
__global__ __launch_bounds__(1024) void topk_kernel(int Npg, int K, int n_next) {
    __shared__ float ss[1024];
    __shared__ int   si[1024];
    int g = blockIdx.x, t = threadIdx.x;

    // zero next layer's degree counters (ordered before remap_count by kernel boundary)
    int zi = g * 1024 + t;
    if (zi < n_next) g_ecnt[zi] = 0;

    float v = (t < Npg) ? g_score[g * Npg + t] : -1e30f;
    int  id = (t < Npg) ? t : -1;

#pragma unroll 1
    for (int k = 2; k <= 1024; k <<= 1) {
        bool desc = ((t & k) == 0);
#pragma unroll 1
        for (int j = k >> 1; j >= 32; j >>= 1) {
            ss[t] = v; si[t] = id;
            __syncthreads();
            float ov = ss[t ^ j]; int oid = si[t ^ j];
            bool keep_max = (desc == ((t & j) == 0));
            bool take = keep_max ? (ov > v) : (ov < v);
            if (take) { v = ov; id = oid; }
            __syncthreads();
        }
        int j0 = (k >> 1 < 16) ? (k >> 1) : 16;
#pragma unroll 1
        for (int j = j0; j >= 1; j >>= 1) {
            float ov = __shfl_xor_sync(0xffffffffu, v, j);
            int  oid = __shfl_xor_sync(0xffffffffu, id, j);
            bool keep_max = (desc == ((t & j) == 0));
            bool take = keep_max ? (ov > v) : (ov < v);
            if (take) { v = ov; id = oid; }
        }
    }
    if (t < Npg) {
        int oldg = g * Npg + id;
        if (t < K) {
            int nw = g * K + t;
            g_newid[oldg] = nw;
            g_oldof[nw]   = oldg;
            g_vals[nw]    = v;
        } else {
            g_newid[oldg] = -1;
        }
    }
}

// ===================== remap edges + count next-layer degrees ===============
__global__ void remap_count_kernel() {
    int e = blockIdx.x * blockDim.x + threadIdx.x;
    if (e >= EDGES) return;
    if (!g_mask[e]) return;
    int s = g_newid[g_src[e]];
    int d = g_newid[g_dst[e]];
    if (s < 0 || d < 0) { g_mask[e] = 0; g_src[e] = 0; g_dst[e] = 0; }
    else                { g_src[e] = s; g_dst[e] = d; atomicAdd(&g_ecnt[d], 1); }
}

// ===================== fused pool-gather + readout ==========================
__global__ __launch_bounds__(512) void poolreadout_kernel(int outsel, int K) {
    __shared__ float smax[4][128];
    __shared__ float ssum[4][128];
    float* xout = sel_out(outsel);
    int g = blockIdx.x, t = threadIdx.x;
    int c = t >> 7, f = t & 127;
    float mx = -1e30f, sm = 0.0f;
    for (int k = c; k < K; k += 4) {
        int nw  = g * K + k;
        int old = g_oldof[nw];
        float v = g_vals[nw];
        float val = g_h[(size_t)old * D + f] * v;
        xout[(size_t)nw * D + f] = val;
        mx = fmaxf(mx, val);
        sm += val;
    }
    smax[c][f] = mx; ssum[c][f] = sm;
    __syncthreads();
    if (c == 0) {
#pragma unroll
        for (int i = 1; i < 4; i++) { mx = fmaxf(mx, smax[i][f]); sm += ssum[i][f]; }
        g_s[g * 256 + f]       += mx;
        g_s[g * 256 + 128 + f] += sm / (float)K;
    }
}

// ===================== final MLP head =======================================
__global__ void mlp_kernel(const float* __restrict__ W1, const float* __restrict__ b1,
                           const float* __restrict__ W2, const float* __restrict__ b2,
                           const float* __restrict__ W3, const float* __restrict__ b3,
                           float* __restrict__ out)
{
    __shared__ float ss[256];
    __shared__ float h1[128];
    __shared__ float h2[64];
    int g = blockIdx.x, t = threadIdx.x;   // 128 threads
    ss[t]       = g_s[g * 256 + t];
    ss[t + 128] = g_s[g * 256 + 128 + t];
    __syncthreads();
    float a = b1[t];
    for (int k = 0; k < 256; k++) a += ss[k] * W1[k * 128 + t];
    h1[t] = fmaxf(a, 0.0f);
    __syncthreads();
    if (t < 64) {
        float a2 = b2[t];
        for (int k = 0; k < 128; k++) a2 += h1[k] * W2[k * 64 + t];
        h2[t] = fmaxf(a2, 0.0f);
    }
    __syncthreads();
    if (t == 0) {
        float s2 = 0.0f;
        for (int i = 0; i < 64; i++) s2 += h2[i] * W3[i];
        out[g] = 1.0f / (1.0f + expf(-(s2 + b3[0])));
    }
}

// ===================== host orchestration ===================================
static void run_layer(const float* x_ext, int xsel, int n, int Npg, int K,
                      const float* bl, const float* pw,
                      int layer, int outsel, int n_next)
{
    escan_kernel<<<BG, 1024>>>(Npg);
    efill_kernel<<<(EDGES + 255) / 256, 256>>>();
    gather_mean_kernel<<<(n * 32 + 255) / 256, 256>>>(x_ext, xsel, n);
    sage_mma_kernel<<<(n + 127) / 128, 256, DYN_BYTES>>>(x_ext, xsel, bl, pw, layer, n);
    topk_kernel<<<BG, 1024>>>(Npg, K, n_next);
    if (n_next > 0) remap_count_kernel<<<(EDGES + 255) / 256, 256>>>();
    poolreadout_kernel<<<BG, 512>>>(outsel, K);
}

extern "C" void kernel_launch(void* const* d_in, const int* in_sizes, int n_in,
                              void* d_out, int out_size)
{
    const float* x   = (const float*)d_in[0];
    const int*   ei  = (const int*)  d_in[1];
    const float* Wl1 = (const float*)d_in[2];
    const float* bl1 = (const float*)d_in[3];
    const float* Wr1 = (const float*)d_in[4];
    const float* pw1 = (const float*)d_in[5];
    const float* Wl2 = (const float*)d_in[6];
    const float* bl2 = (const float*)d_in[7];
    const float* Wr2 = (const float*)d_in[8];
    const float* pw2 = (const float*)d_in[9];
    const float* Wl3 = (const float*)d_in[10];
    const float* bl3 = (const float*)d_in[11];
    const float* Wr3 = (const float*)d_in[12];
    const float* pw3 = (const float*)d_in[13];
    const float* W1  = (const float*)d_in[14];
    const float* b1  = (const float*)d_in[15];
    const float* W2  = (const float*)d_in[16];
    const float* b2  = (const float*)d_in[17];
    const float* W3  = (const float*)d_in[18];
    const float* b3  = (const float*)d_in[19];

    cudaFuncSetAttribute(sage_mma_kernel,
                         cudaFuncAttributeMaxDynamicSharedMemorySize, DYN_BYTES);

    prolog_kernel<<<707, 256>>>(Wl1, Wr1, Wl2, Wr2, Wl3, Wr3, pw1, pw2, pw3);
    init_count_kernel<<<(EDGES + 255) / 256, 256>>>(ei);

    run_layer(x,       0, NN0, NPG0, K1, bl1, pw1, 0, 1, N1);
    run_layer(nullptr, 1, N1,  K1,   K2, bl2, pw2, 1, 2, N2);
    run_layer(nullptr, 2, N2,  K2,   K3, bl3, pw3, 2, 1, 0);

    mlp_kernel<<<BG, 128>>>(W1, b1, W2, b2, W3, b3, (float*)d_out);
}

// round 15
// speedup vs baseline: 1.1623x; 1.1426x over previous
#include <cuda_runtime.h>
#include <cstdint>
#include <math.h>

// Problem constants (fixed by setup_inputs: B=64, N=1024, DEG=16, D=128)
#define D       128
#define BG      64
#define NPG0    1024
#define NN0     (BG * NPG0)        // 65536 nodes layer 1
#define EDGES   (BG * NPG0 * 16)   // 1048576 edges
#define EPG     16384              // CSR capacity per graph
#define K1      820
#define K2      656
#define K3      525
#define N1      (BG * K1)          // 52480
#define N2      (BG * K2)          // 41984
#define N3      (BG * K3)          // 33600

// ---------------- scratch (device globals; no allocation allowed) -----------
__device__ float          g_agg[NN0 * D];     // holds MEAN after gather
__device__ float          g_h[NN0 * D];
__device__ float          g_xa[N1 * D];
__device__ float          g_xb[N2 * D];
__device__ float          g_score[NN0];
__device__ int            g_newid[NN0];
__device__ int            g_oldof[N1];
__device__ float          g_vals[N1];
__device__ int            g_src[EDGES];
__device__ int            g_dst[EDGES];
__device__ unsigned char  g_mask[EDGES];
__device__ int            g_ecnt[NN0];
__device__ int            g_eoff[NN0];
__device__ int            g_ecur[NN0];
__device__ int            g_csr[EDGES];
__device__ float          g_s[BG * 256];
__device__ float          g_invnorm3[3];
__device__ float          g_Bhi[3 * 256 * 128];   // tf32-hi of [Wl;Wr], per layer
__device__ float          g_Blo[3 * 256 * 128];   // tf32-lo of [Wl;Wr], per layer

__device__ __forceinline__ const float* sel_in(const float* ext, int sel) {
    return (sel == 1) ? g_xa : (sel == 2) ? g_xb : ext;
}
__device__ __forceinline__ float* sel_out(int sel) {
    return (sel == 1) ? g_xa : g_xb;
}

// ===================== tf32 mma helpers (sm_80+, no 'a' features) ===========
__device__ __forceinline__ void mma_tf32(float* d,
    uint32_t a0, uint32_t a1, uint32_t a2, uint32_t a3,
    uint32_t b0, uint32_t b1)
{
    asm volatile(
        "mma.sync.aligned.m16n8k8.row.col.f32.tf32.tf32.f32 "
        "{%0,%1,%2,%3}, {%4,%5,%6,%7}, {%8,%9}, {%0,%1,%2,%3};"
        : "+f"(d[0]), "+f"(d[1]), "+f"(d[2]), "+f"(d[3])
        : "r"(a0), "r"(a1), "r"(a2), "r"(a3), "r"(b0), "r"(b1));
}

__device__ __forceinline__ void f32_to_tf32x2(float v, uint32_t& hi, uint32_t& lo) {
    asm("cvt.rna.tf32.f32 %0, %1;" : "=r"(hi) : "f"(v));
    float r = v - __uint_as_float(hi);
    asm("cvt.rna.tf32.f32 %0, %1;" : "=r"(lo) : "f"(r));
}

// ===================== prolog: weight splits + zeroing + invnorms ===========
__global__ void prolog_kernel(
    const float* __restrict__ Wl1, const float* __restrict__ Wr1,
    const float* __restrict__ Wl2, const float* __restrict__ Wr2,
    const float* __restrict__ Wl3, const float* __restrict__ Wr3,
    const float* __restrict__ pw1, const float* __restrict__ pw2,
    const float* __restrict__ pw3)
{
    int b = blockIdx.x, t = threadIdx.x;
    if (b < 384) {
        int i = b * 256 + t;                    // [0, 98304)
        int layer = i >> 15, j = i & 32767;
        int kg = j >> 7, n = j & 127;
        const float* Wl = (layer == 0) ? Wl1 : (layer == 1) ? Wl2 : Wl3;
        const float* Wr = (layer == 0) ? Wr1 : (layer == 1) ? Wr2 : Wr3;
        float v = (kg < 128) ? Wl[(size_t)kg * 128 + n]
                             : Wr[(size_t)(kg - 128) * 128 + n];
        uint32_t hi, lo; f32_to_tf32x2(v, hi, lo);
        g_Bhi[i] = __uint_as_float(hi);
        g_Blo[i] = __uint_as_float(lo);
    } else if (b < 640) {
        int i = (b - 384) * 256 + t;
        if (i < NN0) g_ecnt[i] = 0;
    } else if (b < 704) {
        int i = (b - 640) * 256 + t;
        g_s[i] = 0.0f;
    } else {
        int layer = b - 704;
        const float* pw = (layer == 0) ? pw1 : (layer == 1) ? pw2 : pw3;
        __shared__ float red[256];
        float v = (t < 128) ? pw[t] : 0.0f;
        red[t] = v * v;
        __syncthreads();
        for (int s = 128; s > 0; s >>= 1) {
            if (t < s) red[t] += red[t + s];
            __syncthreads();
        }
        if (t == 0) g_invnorm3[layer] = rsqrtf(red[0]);
    }
}

// ===================== init + layer-1 degree count ==========================
__global__ void init_count_kernel(const int* __restrict__ ei) {
    int i = blockIdx.x * blockDim.x + threadIdx.x;
    if (i < EDGES) {
        int s = ei[i], d = ei[EDGES + i];
        g_src[i] = s;
        g_dst[i] = d;
        g_mask[i] = 1;
        atomicAdd(&g_ecnt[d], 1);
    }
}

// ===================== CSR scan + fill ======================================
__global__ __launch_bounds__(1024) void escan_kernel(int Npg) {
    __shared__ int sc[1024];
    int g = blockIdx.x, t = threadIdx.x;
    int node = g * Npg + t;
    int v = (t < Npg) ? g_ecnt[node] : 0;
    sc[t] = v;
    __syncthreads();
    for (int o = 1; o < 1024; o <<= 1) {
        int a = (t >= o) ? sc[t - o] : 0;
        __syncthreads();
        sc[t] += a;
        __syncthreads();
    }
    if (t < Npg) {
        int off = g * EPG + sc[t] - v;   // exclusive
        g_eoff[node] = off;
        g_ecur[node] = off;
    }
}

__global__ void efill_kernel() {
    int e = blockIdx.x * blockDim.x + threadIdx.x;
    if (e >= EDGES) return;
    if (!g_mask[e]) return;
    int pos = atomicAdd(&g_ecur[g_dst[e]], 1);
    g_csr[pos] = g_src[e];
}

// ===================== gather-mean: g_agg[node] = mean_j x[src_j] ===========
__global__ void gather_mean_kernel(const float* __restrict__ x_ext, int xsel, int n) {
    int gid  = blockIdx.x * blockDim.x + threadIdx.x;
    int node = gid >> 5;
    if (node >= n) return;
    int lane = gid & 31;
    const float* x = sel_in(x_ext, xsel);
    int off = g_eoff[node], cnt = g_ecnt[node];

    float4 acc = make_float4(0.f, 0.f, 0.f, 0.f);
    int i = 0;
    for (; i + 4 <= cnt; i += 4) {
        int s0 = g_csr[off + i], s1 = g_csr[off + i + 1];
        int s2 = g_csr[off + i + 2], s3 = g_csr[off + i + 3];
        float4 v0 = ((const float4*)(x + (size_t)s0 * D))[lane];
        float4 v1 = ((const float4*)(x + (size_t)s1 * D))[lane];
        float4 v2 = ((const float4*)(x + (size_t)s2 * D))[lane];
        float4 v3 = ((const float4*)(x + (size_t)s3 * D))[lane];
        acc.x += v0.x + v1.x + v2.x + v3.x;
        acc.y += v0.y + v1.y + v2.y + v3.y;
        acc.z += v0.z + v1.z + v2.z + v3.z;
        acc.w += v0.w + v1.w + v2.w + v3.w;
    }
    for (; i < cnt; i++) {
        int s = g_csr[off + i];
        float4 v = ((const float4*)(x + (size_t)s * D))[lane];
        acc.x += v.x; acc.y += v.y; acc.z += v.z; acc.w += v.w;
    }
    float inv = 1.0f / (float)max(cnt, 1);
    acc.x *= inv; acc.y *= inv; acc.z *= inv; acc.w *= inv;
    ((float4*)(g_agg + (size_t)node * D))[lane] = acc;
}

// ===================== fused SAGE GEMM (mma.sync tf32x3) + score ============
// R9 memory layout: A in fp32 (single copy), B pre-split hi/lo. 54KB dyn smem.
#define AS_STRIDE 20
#define BS_STRIDE 136
#define AS_WORDS  (128 * AS_STRIDE)
#define BS_WORDS  (16 * BS_STRIDE)
#define DYN_BYTES ((2 * AS_WORDS + 4 * BS_WORDS) * 4)

__device__ __forceinline__ void sage_gload(float4* ra, float4* rbh, float4* rbl,
    int s, int row0, int n, const float* __restrict__ x,
    const float* __restrict__ BhG, const float* __restrict__ BlG, int tid)
{
    int k0 = s * 16;
#pragma unroll
    for (int p = 0; p < 2; p++) {
        int idx = tid + p * 256;
        int r = idx >> 2, c4 = (idx & 3) << 2;
        int node = row0 + r; if (node >= n) node = n - 1;
        float4 v;
        if (k0 < 128) {
            v = *(const float4*)(g_agg + (size_t)node * D + k0 + c4);
        } else {
            v = *(const float4*)(x + (size_t)node * D + (k0 - 128) + c4);
        }
        ra[p] = v;
        int k = idx >> 5, n4 = (idx & 31) << 2;
        size_t woff = (size_t)(k0 + k) * 128 + n4;
        rbh[p] = *(const float4*)(BhG + woff);
        rbl[p] = *(const float4*)(BlG + woff);
    }
}

__device__ __forceinline__ void sage_sstore(const float4* ra, const float4* rbh,
    const float4* rbl, float* Ab, float* Bh, float* Bl, int tid)
{
#pragma unroll
    for (int p = 0; p < 2; p++) {
        int idx = tid + p * 256;
        int r = idx >> 2, c4 = (idx & 3) << 2;
        *(float4*)(Ab + r * AS_STRIDE + c4) = ra[p];
        int k = idx >> 5, n4 = (idx & 31) << 2;
        *(float4*)(Bh + k * BS_STRIDE + n4) = rbh[p];
        *(float4*)(Bl + k * BS_STRIDE + n4) = rbl[p];
    }
}

__device__ __forceinline__ void sage_compute(float acc[2][8][4],
    const float* Ab, const float* Bh, const float* Bl,
    int wm, int wn, int l4, int lq)
{
#pragma unroll
    for (int q = 0; q < 2; q++) {
        int kb = q * 8;
        uint32_t ah[2][4], al[2][4];
#pragma unroll
        for (int i = 0; i < 2; i++) {
            int rbase = wm * 32 + i * 16 + l4;
#pragma unroll
            for (int e = 0; e < 4; e++) {
                int rr = rbase + (e & 1) * 8;
                int kk = kb + lq + (e >> 1) * 4;
                f32_to_tf32x2(Ab[rr * AS_STRIDE + kk], ah[i][e], al[i][e]);
            }
        }
#pragma unroll
        for (int j = 0; j < 8; j++) {
            int nb = wn * 64 + j * 8 + l4;
            uint32_t bh0 = __float_as_uint(Bh[(kb + lq) * BS_STRIDE + nb]);
            uint32_t bh1 = __float_as_uint(Bh[(kb + lq + 4) * BS_STRIDE + nb]);
            uint32_t bl0 = __float_as_uint(Bl[(kb + lq) * BS_STRIDE + nb]);
            uint32_t bl1 = __float_as_uint(Bl[(kb + lq + 4) * BS_STRIDE + nb]);
#pragma unroll
            for (int i = 0; i < 2; i++) {
                mma_tf32(acc[i][j], ah[i][0], ah[i][1], ah[i][2], ah[i][3], bh0, bh1);
                mma_tf32(acc[i][j], ah[i][0], ah[i][1], ah[i][2], ah[i][3], bl0, bl1);
                mma_tf32(acc[i][j], al[i][0], al[i][1], al[i][2], al[i][3], bh0, bh1);
            }
        }
    }
}

__global__ __launch_bounds__(256) void sage_mma_kernel(
    const float* __restrict__ x_ext, int xsel,
    const float* __restrict__ bl, const float* __restrict__ pw,
    int layer, int n)
{
    extern __shared__ float dyn[];
    float* As = dyn;                              // 2 x AS_WORDS (fp32 A)
    float* Bh = dyn + 2 * AS_WORDS;               // 2 x BS_WORDS
    float* Bl = Bh + 2 * BS_WORDS;                // 2 x BS_WORDS
    __shared__ float sBias[128], sPw[128];
    __shared__ float sDot[128][2];

    const float* x = sel_in(x_ext, xsel);
    const float* BhG = g_Bhi + (size_t)layer * 32768;
    const float* BlG = g_Blo + (size_t)layer * 32768;
    int tid = threadIdx.x;
    int wid = tid >> 5, lane = tid & 31;
    int wm = wid & 3, wn = wid >> 2;
    int l4 = lane >> 2, lq = lane & 3;
    int row0 = blockIdx.x * 128;

    if (tid < 128) {
        sBias[tid] = bl[tid];
        sPw[tid]   = pw[tid];
    }
    __syncthreads();

    float acc[2][8][4];
#pragma unroll
    for (int i = 0; i < 2; i++)
#pragma unroll
        for (int j = 0; j < 8; j++)
#pragma unroll
            for (int e = 0; e < 4; e++) acc[i][j][e] = 0.0f;

    float4 ra[2], rbh[2], rbl[2];
    sage_gload(ra, rbh, rbl, 0, row0, n, x, BhG, BlG, tid);
    sage_sstore(ra, rbh, rbl, As, Bh, Bl, tid);
    __syncthreads();

#pragma unroll 1
    for (int s = 0; s < 16; s++) {
        int cur = s & 1, nxt = cur ^ 1;
        if (s < 15) sage_gload(ra, rbh, rbl, s + 1, row0, n, x, BhG, BlG, tid);
        sage_compute(acc, As + cur * AS_WORDS, Bh + cur * BS_WORDS,
                     Bl + cur * BS_WORDS, wm, wn, l4, lq);
        if (s < 15) {
            sage_sstore(ra, rbh, rbl, As + nxt * AS_WORDS,
                        Bh + nxt * BS_WORDS, Bl + nxt * BS_WORDS, tid);
            __syncthreads();
        }
    }

    // ---- epilogue: bias + relu + store h + fused pool-score dot ----
    float dA[2] = {0.0f, 0.0f}, dB[2] = {0.0f, 0.0f};
#pragma unroll
    for (int i = 0; i < 2; i++) {
        int rA = wm * 32 + i * 16 + l4;
        int nodeA = row0 + rA, nodeB = nodeA + 8;
#pragma unroll
        for (int j = 0; j < 8; j++) {
            int c0 = wn * 64 + j * 8 + 2 * lq;
            float o0 = fmaxf(acc[i][j][0] + sBias[c0],     0.0f);
            float o1 = fmaxf(acc[i][j][1] + sBias[c0 + 1], 0.0f);
            float o2 = fmaxf(acc[i][j][2] + sBias[c0],     0.0f);
            float o3 = fmaxf(acc[i][j][3] + sBias[c0 + 1], 0.0f);
            if (nodeA < n) *(float2*)(g_h + (size_t)nodeA * D + c0) = make_float2(o0, o1);
            if (nodeB < n) *(float2*)(g_h + (size_t)nodeB * D + c0) = make_float2(o2, o3);
            dA[i] += o0 * sPw[c0] + o1 * sPw[c0 + 1];
            dB[i] += o2 * sPw[c0] + o3 * sPw[c0 + 1];
        }
    }
#pragma unroll
    for (int o = 1; o <= 2; o <<= 1) {
        dA[0] += __shfl_xor_sync(0xffffffffu, dA[0], o);
        dA[1] += __shfl_xor_sync(0xffffffffu, dA[1], o);
        dB[0] += __shfl_xor_sync(0xffffffffu, dB[0], o);
        dB[1] += __shfl_xor_sync(0xffffffffu, dB[1], o);
    }
    if (lq == 0) {
        sDot[wm * 32 + l4][wn]      = dA[0];
        sDot[wm * 32 + l4 + 8][wn]  = dB[0];
        sDot[wm * 32 + l4 + 16][wn] = dA[1];
        sDot[wm * 32 + l4 + 24][wn] = dB[1];
    }
    __syncthreads();
    if (tid < 128 && row0 + tid < n) {
        float dsum = sDot[tid][0] + sDot[tid][1];
        g_score[row0 + tid] = tanhf(dsum * g_invnorm3[layer]);
    }
}

// ===================== topk (register bitonic) + zero next counts ===========
__global__ __launch_bounds__(1024) void topk_kernel(int Npg, int K, int n_next) {
    __shared__ float ss[1024];
    __shared__ int   si[1024];
    int g = blockIdx.x, t = threadIdx.x;

    // zero next layer's degree counters (ordered before remap_count by kernel boundary)
    int zi = g * 1024 + t;
    if (zi < n_next) g_ecnt[zi] = 0;

    float v = (t < Npg) ? g_score[g * Npg + t] : -1e30f;
    int  id = (t < Npg) ? t : -1;

#pragma unroll 1
    for (int k = 2; k <= 1024; k <<= 1) {
        bool desc = ((t & k) == 0);
#pragma unroll 1
        for (int j = k >> 1; j >= 32; j >>= 1) {
            ss[t] = v; si[t] = id;
            __syncthreads();
            float ov = ss[t ^ j]; int oid = si[t ^ j];
            bool keep_max = (desc == ((t & j) == 0));
            bool take = keep_max ? (ov > v) : (ov < v);
            if (take) { v = ov; id = oid; }
            __syncthreads();
        }
        int j0 = (k >> 1 < 16) ? (k >> 1) : 16;
#pragma unroll 1
        for (int j = j0; j >= 1; j >>= 1) {
            float ov = __shfl_xor_sync(0xffffffffu, v, j);
            int  oid = __shfl_xor_sync(0xffffffffu, id, j);
            bool keep_max = (desc == ((t & j) == 0));
            bool take = keep_max ? (ov > v) : (ov < v);
            if (take) { v = ov; id = oid; }
        }
    }
    if (t < Npg) {
        int oldg = g * Npg + id;
        if (t < K) {
            int nw = g * K + t;
            g_newid[oldg] = nw;
            g_oldof[nw]   = oldg;
            g_vals[nw]    = v;
        } else {
            g_newid[oldg] = -1;
        }
    }
}

// ===================== remap edges + count next-layer degrees ===============
__global__ void remap_count_kernel() {
    int e = blockIdx.x * blockDim.x + threadIdx.x;
    if (e >= EDGES) return;
    if (!g_mask[e]) return;
    int s = g_newid[g_src[e]];
    int d = g_newid[g_dst[e]];
    if (s < 0 || d < 0) { g_mask[e] = 0; g_src[e] = 0; g_dst[e] = 0; }
    else                { g_src[e] = s; g_dst[e] = d; atomicAdd(&g_ecnt[d], 1); }
}

// ===================== pool gather (high-parallelism) + readout =============
__global__ void pool_gather_kernel(int outsel) {
    float* xout = sel_out(outsel);
    int nw = blockIdx.x, t = threadIdx.x;   // 32 threads
    int old = g_oldof[nw];
    float v  = g_vals[nw];
    float4 h4 = ((const float4*)(g_h + (size_t)old * D))[t];
    float4 o = make_float4(h4.x * v, h4.y * v, h4.z * v, h4.w * v);
    ((float4*)(xout + (size_t)nw * D))[t] = o;
}

__global__ __launch_bounds__(512) void readout_kernel(int insel, int K) {
    __shared__ float smax[4][128];
    __shared__ float ssum[4][128];
    const float* xn = sel_in(nullptr, insel);
    int g = blockIdx.x, t = threadIdx.x;
    int c = t >> 7, f = t & 127;
    float mx = -1e30f, sm = 0.0f;
    for (int k = c; k < K; k += 4) {
        float v = xn[((size_t)(g * K + k)) * D + f];
        mx = fmaxf(mx, v);
        sm += v;
    }
    smax[c][f] = mx; ssum[c][f] = sm;
    __syncthreads();
    if (c == 0) {
#pragma unroll
        for (int i = 1; i < 4; i++) { mx = fmaxf(mx, smax[i][f]); sm += ssum[i][f]; }
        g_s[g * 256 + f]       += mx;
        g_s[g * 256 + 128 + f] += sm / (float)K;
    }
}

// ===================== final MLP head =======================================
__global__ void mlp_kernel(const float* __restrict__ W1, const float* __restrict__ b1,
                           const float* __restrict__ W2, const float* __restrict__ b2,
                           const float* __restrict__ W3, const float* __restrict__ b3,
                           float* __restrict__ out)
{
    __shared__ float ss[256];
    __shared__ float h1[128];
    __shared__ float h2[64];
    int g = blockIdx.x, t = threadIdx.x;   // 128 threads
    ss[t]       = g_s[g * 256 + t];
    ss[t + 128] = g_s[g * 256 + 128 + t];
    __syncthreads();
    float a = b1[t];
    for (int k = 0; k < 256; k++) a += ss[k] * W1[k * 128 + t];
    h1[t] = fmaxf(a, 0.0f);
    __syncthreads();
    if (t < 64) {
        float a2 = b2[t];
        for (int k = 0; k < 128; k++) a2 += h1[k] * W2[k * 64 + t];
        h2[t] = fmaxf(a2, 0.0f);
    }
    __syncthreads();
    if (t == 0) {
        float s2 = 0.0f;
        for (int i = 0; i < 64; i++) s2 += h2[i] * W3[i];
        out[g] = 1.0f / (1.0f + expf(-(s2 + b3[0])));
    }
}

// ===================== host orchestration ===================================
static void run_layer(const float* x_ext, int xsel, int n, int Npg, int K,
                      const float* bl, const float* pw,
                      int layer, int outsel, int n_next)
{
    escan_kernel<<<BG, 1024>>>(Npg);
    efill_kernel<<<(EDGES + 255) / 256, 256>>>();
    gather_mean_kernel<<<(n * 32 + 255) / 256, 256>>>(x_ext, xsel, n);
    sage_mma_kernel<<<(n + 127) / 128, 256, DYN_BYTES>>>(x_ext, xsel, bl, pw, layer, n);
    topk_kernel<<<BG, 1024>>>(Npg, K, n_next);
    if (n_next > 0) remap_count_kernel<<<(EDGES + 255) / 256, 256>>>();
    pool_gather_kernel<<<BG * K, 32>>>(outsel);
    readout_kernel<<<BG, 512>>>(outsel, K);
}

extern "C" void kernel_launch(void* const* d_in, const int* in_sizes, int n_in,
                              void* d_out, int out_size)
{
    const float* x   = (const float*)d_in[0];
    const int*   ei  = (const int*)  d_in[1];
    const float* Wl1 = (const float*)d_in[2];
    const float* bl1 = (const float*)d_in[3];
    const float* Wr1 = (const float*)d_in[4];
    const float* pw1 = (const float*)d_in[5];
    const float* Wl2 = (const float*)d_in[6];
    const float* bl2 = (const float*)d_in[7];
    const float* Wr2 = (const float*)d_in[8];
    const float* pw2 = (const float*)d_in[9];
    const float* Wl3 = (const float*)d_in[10];
    const float* bl3 = (const float*)d_in[11];
    const float* Wr3 = (const float*)d_in[12];
    const float* pw3 = (const float*)d_in[13];
    const float* W1  = (const float*)d_in[14];
    const float* b1  = (const float*)d_in[15];
    const float* W2  = (const float*)d_in[16];
    const float* b2  = (const float*)d_in[17];
    const float* W3  = (const float*)d_in[18];
    const float* b3  = (const float*)d_in[19];

    cudaFuncSetAttribute(sage_mma_kernel,
                         cudaFuncAttributeMaxDynamicSharedMemorySize, DYN_BYTES);

    prolog_kernel<<<707, 256>>>(Wl1, Wr1, Wl2, Wr2, Wl3, Wr3, pw1, pw2, pw3);
    init_count_kernel<<<(EDGES + 255) / 256, 256>>>(ei);

    run_layer(x,       0, NN0, NPG0, K1, bl1, pw1, 0, 1, N1);
    run_layer(nullptr, 1, N1,  K1,   K2, bl2, pw2, 1, 2, N2);
    run_layer(nullptr, 2, N2,  K2,   K3, bl3, pw3, 2, 1, 0);

    mlp_kernel<<<BG, 128>>>(W1, b1, W2, b2, W3, b3, (float*)d_out);
}